// round 2
// baseline (speedup 1.0000x reference)
#include <cuda_runtime.h>

#define NB   4096   // batches
#define NT   24     // history steps
#define NN   7      // nodes
#define DYN  6
#define STAT 5
#define NIN  11     // DYN + STAT
#define H    64
#define FUT  48
#define G4   256    // 4*H
#define NTHREADS 512

struct alignas(16) Smem {
    float enc_w[NIN * H];   // 704
    float g1w[H * H];       // 4096
    float g2w[H * H];       // 4096
    float dw1[H * 32];      // 2048
    float dw2[32 * DYN];    // 192
    float enc_b[H];
    float g1b[H];
    float g2b[H];
    float bsum[G4];         // b_ih + b_hh
    float db1[32];
    float db2[8];
    float adjn[NN * 8];     // padded rows
    float dvec[8];
    float xs[80];           // 7*11 = 77, padded
    float bufA[NN * H];     // 448
    float bufB[NN * H];
    float hx[NN * H];
    float cx[NN * H];
    float gbuf[NN * G4];    // 1792
    float dbuf[NN * 32];    // 224
    float pred[NN * DYN + 2];
    float stat[NN * STAT + 3];
};

__device__ __forceinline__ float sigf(float x) {
    return 1.0f / (1.0f + __expf(-x));
}
__device__ __forceinline__ float tanhfast(float x) {
    // 2*sigmoid(2x) - 1; exact limits at +-inf via expf saturation
    return 2.0f / (1.0f + __expf(-2.0f * x)) - 1.0f;
}

__global__ void __launch_bounds__(NTHREADS, 1) stgnn_kernel(
    const float* __restrict__ x_history, const float* __restrict__ adj,
    const float* __restrict__ enc_w, const float* __restrict__ enc_b,
    const float* __restrict__ g1w, const float* __restrict__ g1b,
    const float* __restrict__ g2w, const float* __restrict__ g2b,
    const float* __restrict__ w_ih, const float* __restrict__ w_hh,
    const float* __restrict__ b_ih, const float* __restrict__ b_hh,
    const float* __restrict__ dw1, const float* __restrict__ db1,
    const float* __restrict__ dw2, const float* __restrict__ db2,
    float* __restrict__ out)
{
    extern __shared__ unsigned char smraw[];
    Smem* S = reinterpret_cast<Smem*>(smraw);

    const int tid  = threadIdx.x;
    const int b    = blockIdx.x;
    const int lane = tid & 31;
    const int wrp  = tid >> 5;
    const int col  = wrp * 16 + (lane >> 1);  // gate column 0..255
    const int par  = lane & 1;                // 0: s2 @ w_ih half, 1: hx @ w_hh half

    // ---- one-time: stage small weights into smem ----
    for (int i = tid; i < NIN * H; i += NTHREADS) S->enc_w[i] = enc_w[i];
    for (int i = tid; i < H * H; i += NTHREADS) { S->g1w[i] = g1w[i]; S->g2w[i] = g2w[i]; }
    for (int i = tid; i < H * 32; i += NTHREADS) S->dw1[i] = dw1[i];
    for (int i = tid; i < 32 * DYN; i += NTHREADS) S->dw2[i] = dw2[i];
    if (tid < H)  { S->enc_b[tid] = enc_b[tid]; S->g1b[tid] = g1b[tid]; S->g2b[tid] = g2b[tid]; }
    if (tid < G4) S->bsum[tid] = b_ih[tid] + b_hh[tid];
    if (tid < 32)  S->db1[tid] = db1[tid];
    if (tid < DYN) S->db2[tid] = db2[tid];

    // ---- adjacency: diag=1, row-sum clip, symmetric normalize ----
    if (tid < 49) {
        int i = tid / 7, j = tid % 7;
        float v = adj[(size_t)b * 49 + tid];
        if (i == j) v = 1.0f;
        S->adjn[i * 8 + j] = v;
    }
    __syncthreads();
    if (tid < 7) {
        float s = 0.f;
        #pragma unroll
        for (int j = 0; j < 7; j++) s += S->adjn[tid * 8 + j];
        S->dvec[tid] = rsqrtf(fmaxf(s, 1.0f));
    }
    __syncthreads();
    if (tid < 49) {
        int i = tid / 7, j = tid % 7;
        S->adjn[i * 8 + j] *= S->dvec[i] * S->dvec[j];
    }

    // ---- init state ----
    for (int i = tid; i < NN * H; i += NTHREADS) { S->hx[i] = 0.f; S->cx[i] = 0.f; }
    if (tid < 77) {
        int n = tid / NIN, k = tid % NIN;
        float v = x_history[((size_t)b * NT + (NT - 1)) * 77 + tid];
        if (k < DYN) S->pred[n * DYN + k] = v;
        else         S->stat[n * STAT + (k - DYN)] = v;
    }

    // ---- register-cache LSTM weights: this lane's gate-column half ----
    float wreg[64];
    {
        const float* wp = (par == 0 ? w_ih : w_hh) + (size_t)col * H;
        const float4* wp4 = reinterpret_cast<const float4*>(wp);
        #pragma unroll
        for (int q = 0; q < 16; q++) {
            float4 v = wp4[q];
            wreg[4 * q + 0] = v.x; wreg[4 * q + 1] = v.y;
            wreg[4 * q + 2] = v.z; wreg[4 * q + 3] = v.w;
        }
    }
    __syncthreads();

    const int n448 = tid >> 6;   // node index for 448-wide phases
    const int h448 = tid & 63;   // feature index

    for (int step = 0; step < NT + FUT; ++step) {
        // ---- build x_t ----
        if (step < NT) {
            if (tid < 77) S->xs[tid] = x_history[((size_t)b * NT + step) * 77 + tid];
        } else {
            if (tid < 77) {
                int n = tid / NIN, k = tid % NIN;
                S->xs[tid] = (k < DYN) ? S->pred[n * DYN + k]
                                       : S->stat[n * STAT + (k - DYN)];
            }
        }
        __syncthreads();

        // ---- encoder: relu(x @ enc_w + b) -> bufA ----
        if (tid < 448) {
            float acc = S->enc_b[h448];
            #pragma unroll
            for (int k = 0; k < NIN; k++)
                acc += S->xs[n448 * NIN + k] * S->enc_w[k * H + h448];
            S->bufA[tid] = fmaxf(acc, 0.f);
        }
        __syncthreads();

        // ---- gcn1: t = bufA @ g1w -> bufB ----
        if (tid < 448) {
            float acc = 0.f;
            const float4* arow = reinterpret_cast<const float4*>(S->bufA + n448 * H);
            #pragma unroll
            for (int q = 0; q < 16; q++) {
                float4 a = arow[q];
                acc += a.x * S->g1w[(4 * q + 0) * H + h448];
                acc += a.y * S->g1w[(4 * q + 1) * H + h448];
                acc += a.z * S->g1w[(4 * q + 2) * H + h448];
                acc += a.w * S->g1w[(4 * q + 3) * H + h448];
            }
            S->bufB[tid] = acc;
        }
        __syncthreads();
        // mix: s1 = relu(adjn @ t + b1) -> bufA
        if (tid < 448) {
            float acc = S->g1b[h448];
            #pragma unroll
            for (int j = 0; j < 7; j++)
                acc += S->adjn[n448 * 8 + j] * S->bufB[j * H + h448];
            S->bufA[tid] = fmaxf(acc, 0.f);
        }
        __syncthreads();

        // ---- gcn2: t = bufA @ g2w -> bufB ----
        if (tid < 448) {
            float acc = 0.f;
            const float4* arow = reinterpret_cast<const float4*>(S->bufA + n448 * H);
            #pragma unroll
            for (int q = 0; q < 16; q++) {
                float4 a = arow[q];
                acc += a.x * S->g2w[(4 * q + 0) * H + h448];
                acc += a.y * S->g2w[(4 * q + 1) * H + h448];
                acc += a.z * S->g2w[(4 * q + 2) * H + h448];
                acc += a.w * S->g2w[(4 * q + 3) * H + h448];
            }
            S->bufB[tid] = acc;
        }
        __syncthreads();
        // mix: s2 = relu(adjn @ t + b2) -> bufA
        if (tid < 448) {
            float acc = S->g2b[h448];
            #pragma unroll
            for (int j = 0; j < 7; j++)
                acc += S->adjn[n448 * 8 + j] * S->bufB[j * H + h448];
            S->bufA[tid] = fmaxf(acc, 0.f);
        }
        __syncthreads();

        // ---- LSTM gates: g = s2 @ w_ih^T + hx @ w_hh^T (biases added later) ----
        {
            const float* src = par ? S->hx : S->bufA;  // odd lanes: hx half
            float tot[7];
            #pragma unroll
            for (int n = 0; n < 7; n++) {
                const float4* row = reinterpret_cast<const float4*>(src + n * H);
                float acc = 0.f;
                #pragma unroll
                for (int q = 0; q < 16; q++) {
                    float4 v = row[q];
                    acc += v.x * wreg[4 * q + 0] + v.y * wreg[4 * q + 1]
                         + v.z * wreg[4 * q + 2] + v.w * wreg[4 * q + 3];
                }
                tot[n] = acc + __shfl_xor_sync(0xffffffffu, acc, 1);
            }
            #pragma unroll
            for (int n = 0; n < 7; n++) {
                if ((n < 4) == (par == 0))
                    S->gbuf[n * G4 + col] = tot[n];
            }
        }
        __syncthreads();

        // ---- LSTM update ----
        if (tid < 448) {
            float gi = S->gbuf[n448 * G4 +       h448] + S->bsum[      h448];
            float gf = S->gbuf[n448 * G4 +  64 + h448] + S->bsum[ 64 + h448];
            float gg = S->gbuf[n448 * G4 + 128 + h448] + S->bsum[128 + h448];
            float go = S->gbuf[n448 * G4 + 192 + h448] + S->bsum[192 + h448];
            float c = sigf(gf) * S->cx[tid] + sigf(gi) * tanhfast(gg);
            S->cx[tid] = c;
            S->hx[tid] = sigf(go) * tanhfast(c);
        }
        __syncthreads();

        // ---- decoder (future steps only) ----
        if (step >= NT) {
            if (tid < 224) {
                int n = tid >> 5, j = tid & 31;
                float acc = S->db1[j];
                const float4* hrow = reinterpret_cast<const float4*>(S->hx + n * H);
                #pragma unroll
                for (int q = 0; q < 16; q++) {
                    float4 v = hrow[q];
                    acc += v.x * S->dw1[(4 * q + 0) * 32 + j]
                         + v.y * S->dw1[(4 * q + 1) * 32 + j]
                         + v.z * S->dw1[(4 * q + 2) * 32 + j]
                         + v.w * S->dw1[(4 * q + 3) * 32 + j];
                }
                S->dbuf[tid] = fmaxf(acc, 0.f);
            }
            __syncthreads();
            if (tid < 42) {
                int n = tid / 6, d = tid % 6;
                float acc = S->db2[d];
                #pragma unroll
                for (int j = 0; j < 32; j++)
                    acc += S->dbuf[n * 32 + j] * S->dw2[j * DYN + d];
                float r = tanhfast(acc) * 0.05f;
                float p = S->pred[tid] + r;
                p = fminf(fmaxf(p, 0.f), 1.0f);
                S->pred[tid] = p;
                out[(((size_t)b * FUT + (step - NT)) * NN + n) * DYN + d] = p;
            }
            __syncthreads();
        }
    }
}

extern "C" void kernel_launch(void* const* d_in, const int* in_sizes, int n_in,
                              void* d_out, int out_size)
{
    (void)in_sizes; (void)n_in; (void)out_size;
    cudaFuncSetAttribute(stgnn_kernel,
                         cudaFuncAttributeMaxDynamicSharedMemorySize,
                         (int)sizeof(Smem));
    stgnn_kernel<<<NB, NTHREADS, sizeof(Smem)>>>(
        (const float*)d_in[0],  (const float*)d_in[1],
        (const float*)d_in[2],  (const float*)d_in[3],
        (const float*)d_in[4],  (const float*)d_in[5],
        (const float*)d_in[6],  (const float*)d_in[7],
        (const float*)d_in[8],  (const float*)d_in[9],
        (const float*)d_in[10], (const float*)d_in[11],
        (const float*)d_in[12], (const float*)d_in[13],
        (const float*)d_in[14], (const float*)d_in[15],
        (float*)d_out);
}